// round 14
// baseline (speedup 1.0000x reference)
#include <cuda_runtime.h>
#include <cuda_bf16.h>
#include <math.h>
#include <cstdint>

#define D_MODEL 512
#define D_HID   1024
#define NTOK    4096
#define NEXP    64
#define TOPK    8
#define NNULL   64
#define T0      3872
#define NTAIL   (NTOK - T0)          // 224
#define CAPL    768

// metadata region (floats) at reg = out + T0*D_MODEL; overwritten by tail pass later
#define R_CNT   0                    // int[64]: ALL real picks (aux)
#define R_LLEN  64                   // int[64]: list length (tokens < T0)
#define R_PSUM  128                  // float[64]
#define R_LSE2  192
#define R_NULL  193
#define R_TOK   256                  // int[64*CAPL]
#define R_WGT   (R_TOK + NEXP*CAPL)
#define R_END   (R_WGT + NEXP*CAPL)  // 98560 < 224*512

// dynamic smem layout (bytes) for fused FFN
#define SXH  0
#define SXL  2560
#define SW0H 5120
#define SW0L 7680
#define SW1H 10240
#define SW1L 12800
#define SHH  15360
#define SHL  17920
#define SW2H 20480
#define SW2L 61440
#define STOK 102400
#define SWGT 102528
#define SMEM_TOT 102656

// ===================== PTX helpers ==============================================
__device__ __forceinline__ uint32_t smem_u32(const void* p) {
  uint32_t a;
  asm("{ .reg .u64 t; cvta.to.shared.u64 t, %1; cvt.u32.u64 %0, t; }" : "=r"(a) : "l"(p));
  return a;
}
#define LDSM4(r, a) \
  asm volatile("ldmatrix.sync.aligned.m8n8.x4.shared.b16 {%0,%1,%2,%3}, [%4];" \
    : "=r"((r)[0]), "=r"((r)[1]), "=r"((r)[2]), "=r"((r)[3]) : "r"(a))
#define LDSM2(r, a) \
  asm volatile("ldmatrix.sync.aligned.m8n8.x2.shared.b16 {%0,%1}, [%2];" \
    : "=r"((r)[0]), "=r"((r)[1]) : "r"(a))
#define LDSM2T(r, a) \
  asm volatile("ldmatrix.sync.aligned.m8n8.x2.trans.shared.b16 {%0,%1}, [%2];" \
    : "=r"((r)[0]), "=r"((r)[1]) : "r"(a))
#define MMA16816(c, a, b) \
  asm volatile("mma.sync.aligned.m16n8k16.row.col.f32.bf16.bf16.f32 " \
    "{%0,%1,%2,%3}, {%4,%5,%6,%7}, {%8,%9}, {%0,%1,%2,%3};" \
    : "+f"((c)[0]), "+f"((c)[1]), "+f"((c)[2]), "+f"((c)[3]) \
    : "r"((a)[0]), "r"((a)[1]), "r"((a)[2]), "r"((a)[3]), "r"((b)[0]), "r"((b)[1]))

__device__ __forceinline__ void split2(float v, __nv_bfloat16& h, __nv_bfloat16& l) {
  h = __float2bfloat16_rn(v);
  l = __float2bfloat16_rn(v - __bfloat162float(h));
}
__device__ __forceinline__ void split_store(char* bh, char* bl, uint32_t off, float4 v) {
  __nv_bfloat16 h0,l0,h1,l1,h2,l2,h3,l3;
  split2(v.x,h0,l0); split2(v.y,h1,l1); split2(v.z,h2,l2); split2(v.w,h3,l3);
  *(__nv_bfloat162*)(bh + off)     = __halves2bfloat162(h0,h1);
  *(__nv_bfloat162*)(bh + off + 4) = __halves2bfloat162(h2,h3);
  *(__nv_bfloat162*)(bl + off)     = __halves2bfloat162(l0,l1);
  *(__nv_bfloat162*)(bl + off + 4) = __halves2bfloat162(l2,l3);
}
__device__ __forceinline__ float siluf(float v) { return v / (1.f + __expf(-v)); }

// top-8 over [real(0..63), 64 null copies]; returns sel (-1 = null), normalized w
__device__ void top8(const float* lg, float nv, int* sel, float* wout, int* nnull) {
  unsigned long long used = 0ull;
  float sl[TOPK]; int nn = 0;
  for (int j = 0; j < TOPK; j++) {
    float best = -1e30f; int bi = -1;
    for (int e = 0; e < NEXP; e++)
      if (!((used >> e) & 1ull) && lg[e] > best) { best = lg[e]; bi = e; }
    if (nv > best) { sel[j] = -1; sl[j] = nv; nn++; }
    else           { sel[j] = bi; sl[j] = best; used |= (1ull << bi); }
  }
  float m = -1e30f;
  for (int j = 0; j < TOPK; j++) if (sel[j] >= 0 && sl[j] > m) m = sl[j];
  float ss = 0.f;
  for (int j = 0; j < TOPK; j++) { wout[j] = (sel[j] >= 0) ? __expf(sl[j]-m) : 0.f; ss += wout[j]; }
  float inv = (ss > 1e-30f) ? 1.f/ss : 0.f;
  for (int j = 0; j < TOPK; j++) wout[j] *= inv;
  *nnull = nn;
}

// ===================== fused FFN tile: 32 tokens x full D_MODEL =================
// TR=true : routed — W0/W1 [D][H] k-major, W2 [H][D] k-major; rows from smem
//           token list (STOK/SWGT); weighted atomicAdd into out.
// TR=false: shared — W0/W1 [H][D] n-major, W2 [D][H] n-major; rows mbase+..;
//           direct stores.
template<bool TR>
__device__ void ffn_tile(char* sm, const float* __restrict__ x,
    const float* __restrict__ W0, const float* __restrict__ W1,
    const float* __restrict__ W2, float* __restrict__ out, int mbase) {
  int tid = threadIdx.x, lane = tid & 31, wid = tid >> 5;
  uint32_t smb = smem_u32(sm);
  const int*   stok = (const int*)(sm + STOK);
  const float* swgt = (const float*)(sm + SWGT);
  int wm1 = (wid & 1)*16, wn1 = (wid >> 1)*8;     // stage1: 32x32, warp 16x8
  int wm2 = (wid & 1)*16, wn2 = (wid >> 1)*128;   // stage2: 32x512, warp 16x128

  float acc2[16][4];
  #pragma unroll
  for (int j = 0; j < 16; j++)
    #pragma unroll
    for (int q = 0; q < 4; q++) acc2[j][q] = 0.f;

  for (int hc = 0; hc < D_HID/32; hc++) {
    float acc1[2][4];
    #pragma unroll
    for (int mt = 0; mt < 2; mt++)
      #pragma unroll
      for (int q = 0; q < 4; q++) acc1[mt][q] = 0.f;

    for (int kc = 0; kc < D_MODEL/32; kc++) {
      __syncthreads();
      { // x tile 32x32
        int row = tid >> 3, c4 = tid & 7;
        float4 v = make_float4(0.f,0.f,0.f,0.f);
        int tok = TR ? stok[row] : (mbase + row);
        if (!TR || tok >= 0)
          v = *(const float4*)(x + (size_t)tok*D_MODEL + kc*32 + c4*4);
        split_store(sm+SXH, sm+SXL, (uint32_t)row*80 + c4*8, v);
      }
      #pragma unroll
      for (int mt = 0; mt < 2; mt++) { // W0/W1 tiles 32x32
        const float* W = mt ? W1 : W0;
        char* bh = sm + (mt ? SW1H : SW0H);
        char* bl = sm + (mt ? SW1L : SW0L);
        int row = tid >> 3, c4 = tid & 7;
        float4 v = TR
          ? *(const float4*)(W + (size_t)(kc*32+row)*D_HID + hc*32 + c4*4)
          : *(const float4*)(W + (size_t)(hc*32+row)*D_MODEL + kc*32 + c4*4);
        split_store(bh, bl, (uint32_t)row*80 + c4*8, v);
      }
      __syncthreads();
      #pragma unroll
      for (int ks = 0; ks < 2; ks++) {
        uint32_t ah[4], al[4];
        uint32_t ao = (uint32_t)(wm1 + (lane & 15))*80 + (ks*16 + (lane >> 4)*8)*2;
        LDSM4(ah, smb+SXH+ao); LDSM4(al, smb+SXL+ao);
        #pragma unroll
        for (int mt = 0; mt < 2; mt++) {
          uint32_t ubh = smb + (mt ? SW1H : SW0H), ubl = smb + (mt ? SW1L : SW0L);
          uint32_t bh[2], bl2[2];
          if (TR) {
            uint32_t bb = (uint32_t)(ks*16 + (lane & 15))*80 + wn1*2;
            LDSM2T(bh, ubh+bb); LDSM2T(bl2, ubl+bb);
          } else {
            uint32_t bb = (uint32_t)(wn1 + (lane & 7))*80 + (ks*16 + ((lane >> 3) & 1)*8)*2;
            LDSM2(bh, ubh+bb); LDSM2(bl2, ubl+bb);
          }
          MMA16816(acc1[mt], ah, bh);
          MMA16816(acc1[mt], ah, bl2);
          MMA16816(acc1[mt], al, bh);
        }
      }
    }
    // h = silu(gate)*up -> smem (32x32, stride 80)
    { int r = lane >> 2, c = (lane & 3)*2;
      #pragma unroll
      for (int half = 0; half < 2; half++) {
        int row = wm1 + r + half*8;
        float h0 = siluf(acc1[0][half*2+0]) * acc1[1][half*2+0];
        float h1 = siluf(acc1[0][half*2+1]) * acc1[1][half*2+1];
        __nv_bfloat16 hh0,hl0,hh1,hl1;
        split2(h0,hh0,hl0); split2(h1,hh1,hl1);
        uint32_t off = (uint32_t)row*80 + (wn1 + c)*2;
        *(__nv_bfloat162*)(sm+SHH+off) = __halves2bfloat162(hh0,hh1);
        *(__nv_bfloat162*)(sm+SHL+off) = __halves2bfloat162(hl0,hl1);
      } }
    // W2 tile
    #pragma unroll
    for (int it = 0; it < 16; it++) {
      int idx = tid + it*256;
      if (TR) {
        int row = idx >> 7, c4 = idx & 127;   // 32 k-rows x 512 n, stride 1040
        float4 v = *(const float4*)(W2 + (size_t)(hc*32+row)*D_MODEL + c4*4);
        split_store(sm+SW2H, sm+SW2L, (uint32_t)row*1040 + c4*8, v);
      } else {
        int row = idx >> 3, c4 = idx & 7;     // 512 n-rows x 32 k, stride 80
        float4 v = *(const float4*)(W2 + (size_t)row*D_HID + hc*32 + c4*4);
        split_store(sm+SW2H, sm+SW2L, (uint32_t)row*80 + c4*8, v);
      } }
    __syncthreads();
    #pragma unroll
    for (int ks = 0; ks < 2; ks++) {
      uint32_t ah[4], al[4];
      uint32_t ao = (uint32_t)(wm2 + (lane & 15))*80 + (ks*16 + (lane >> 4)*8)*2;
      LDSM4(ah, smb+SHH+ao); LDSM4(al, smb+SHL+ao);
      #pragma unroll
      for (int j = 0; j < 16; j++) {
        uint32_t bh[2], bl2[2];
        if (TR) {
          uint32_t bb = (uint32_t)(ks*16 + (lane & 15))*1040 + (wn2 + j*8)*2;
          LDSM2T(bh, smb+SW2H+bb); LDSM2T(bl2, smb+SW2L+bb);
        } else {
          uint32_t bb = (uint32_t)(wn2 + j*8 + (lane & 7))*80 + (ks*16 + ((lane >> 3) & 1)*8)*2;
          LDSM2(bh, smb+SW2H+bb); LDSM2(bl2, smb+SW2L+bb);
        }
        MMA16816(acc2[j], ah, bh);
        MMA16816(acc2[j], ah, bl2);
        MMA16816(acc2[j], al, bh);
      } }
    __syncthreads();
  }
  // epilogue
  int r = lane >> 2, c = (lane & 3)*2;
  #pragma unroll
  for (int half = 0; half < 2; half++) {
    int rl = wm2 + r + half*8;
    if (TR) {
      int tok = stok[rl];
      if (tok < 0) continue;
      float w = swgt[rl];
      float* dst = out + (size_t)tok*D_MODEL;
      #pragma unroll
      for (int j = 0; j < 16; j++) {
        int col = wn2 + j*8 + c;
        atomicAdd(dst + col,     acc2[j][half*2+0]*w);
        atomicAdd(dst + col + 1, acc2[j][half*2+1]*w);
      }
    } else {
      float* dst = out + (size_t)(mbase + rl)*D_MODEL;
      #pragma unroll
      for (int j = 0; j < 16; j++) {
        int col = wn2 + j*8 + c;
        *(float2*)(dst + col) = make_float2(acc2[j][half*2+0], acc2[j][half*2+1]);
      }
    }
  }
}

// ===================== kernels ==================================================
__global__ void k_zero_region(float* __restrict__ reg) {
  int i = blockIdx.x*256 + threadIdx.x;
  if (i < R_END) reg[i] = 0.f;
}

__global__ __launch_bounds__(128) void k_router(const float* __restrict__ x,
    const float* __restrict__ gw, const float* __restrict__ bias,
    const float* __restrict__ nullp, float* __restrict__ reg) {
  __shared__ float xs[D_MODEL];
  __shared__ float lg[NEXP];
  int t = blockIdx.x, tid = threadIdx.x;
  *(float4*)(xs + tid*4) = *(const float4*)(x + (size_t)t*D_MODEL + tid*4);
  __syncthreads();
  if (tid < NEXP) {
    const float* w = gw + (size_t)tid*D_MODEL;
    float s = 0.f;
    #pragma unroll 8
    for (int k = 0; k < D_MODEL; k += 4) {
      float4 wv = *(const float4*)(w + k);
      s += xs[k]*wv.x + xs[k+1]*wv.y + xs[k+2]*wv.z + xs[k+3]*wv.w;
    }
    lg[tid] = s + bias[tid];
  }
  __syncthreads();
  if (tid == 0) {
    int*   cnt   = (int*)(reg + R_CNT);
    int*   llen  = (int*)(reg + R_LLEN);
    float* psum  = reg + R_PSUM;
    int*   ltok  = (int*)(reg + R_TOK);
    float* lwgt  = reg + R_WGT;
    float nv = *nullp;
    int sel[TOPK]; float wj[TOPK]; int nn;
    top8(lg, nv, sel, wj, &nn);
    for (int j = 0; j < TOPK; j++) {
      if (sel[j] >= 0) {
        atomicAdd(&cnt[sel[j]], 1);
        if (t < T0) {
          int pos = atomicAdd(&llen[sel[j]], 1);
          if (pos < CAPL) {
            ltok[sel[j]*CAPL + pos] = t;
            lwgt[sel[j]*CAPL + pos] = wj[j];
          }
        }
      }
    }
    if (nn) atomicAdd((int*)(reg + R_NULL), nn);
    float mr = -1e30f;
    for (int e = 0; e < NEXP; e++) if (lg[e] > mr) mr = lg[e];
    float Z = 0.f;
    for (int e = 0; e < NEXP; e++) Z += __expf(lg[e]-mr);
    float invZ = 1.f/Z;
    for (int e = 0; e < NEXP; e++) atomicAdd(&psum[e], __expf(lg[e]-mr)*invZ);
    float m2 = fmaxf(mr, nv);
    float Z2 = Z*__expf(mr-m2) + (float)NNULL*__expf(nv-m2);
    float lse = m2 + logf(Z2);
    atomicAdd(reg + R_LSE2, lse*lse);
  }
}

__global__ __launch_bounds__(256) void k_ffn_shared(const float* __restrict__ x,
    const float* __restrict__ Wsg, const float* __restrict__ Wsu,
    const float* __restrict__ Wsd, float* __restrict__ out, int mb) {
  extern __shared__ char sm[];
  ffn_tile<false>(sm, x, Wsg, Wsu, Wsd, out, mb + blockIdx.x*32);
}

__global__ __launch_bounds__(256) void k_ffn_routed(const float* __restrict__ x,
    const float* __restrict__ Wg, const float* __restrict__ Wu,
    const float* __restrict__ Wd, float* __restrict__ out,
    const float* __restrict__ reg) {
  extern __shared__ char sm[];
  int e = blockIdx.y;
  int len = min(((const int*)(reg + R_LLEN))[e], CAPL);
  int m0 = blockIdx.x*32;
  if (m0 >= len) return;
  if (threadIdx.x < 32) {
    int m = m0 + threadIdx.x;
    ((int*)(sm+STOK))[threadIdx.x]   = (m < len) ? ((const int*)(reg + R_TOK))[e*CAPL + m] : -1;
    ((float*)(sm+SWGT))[threadIdx.x] = (m < len) ? (reg + R_WGT)[e*CAPL + m] : 0.f;
  }
  __syncthreads();
  ffn_tile<true>(sm, x,
      Wg + (size_t)e*D_MODEL*D_HID, Wu + (size_t)e*D_MODEL*D_HID,
      Wd + (size_t)e*D_HID*D_MODEL, out, 0);
}

// one block per expert: recompute routing for tail tokens, run routed FFN on them
__global__ __launch_bounds__(256) void k_cleanup(const float* __restrict__ x,
    const float* __restrict__ gw, const float* __restrict__ bias,
    const float* __restrict__ nullp,
    const float* __restrict__ Wg, const float* __restrict__ Wu,
    const float* __restrict__ Wd, float* __restrict__ out) {
  extern __shared__ char sm[];
  __shared__ float clg[8][NEXP];
  __shared__ int   ctok[NTAIL];
  __shared__ float cwgt[NTAIL];
  __shared__ int   ccnt;
  int tid = threadIdx.x, lane = tid & 31, wid = tid >> 5;
  int e = blockIdx.x;
  if (tid == 0) ccnt = 0;
  __syncthreads();
  float nv = *nullp;
  for (int ti = wid; ti < NTAIL; ti += 8) {
    int t = T0 + ti;
    const float4* xr = (const float4*)(x + (size_t)t*D_MODEL);
    #pragma unroll
    for (int sub = 0; sub < 2; sub++) {
      int e2 = lane + sub*32;
      const float4* wr = (const float4*)(gw + (size_t)e2*D_MODEL);
      float s = 0.f;
      #pragma unroll 8
      for (int k = 0; k < D_MODEL/4; k++) {
        float4 a = xr[k], b = wr[k];
        s += a.x*b.x + a.y*b.y + a.z*b.z + a.w*b.w;
      }
      clg[wid][e2] = s + bias[e2];
    }
    __syncwarp();
    if (lane == 0) {
      int sel[TOPK]; float wj[TOPK]; int nn;
      top8(clg[wid], nv, sel, wj, &nn);
      for (int j = 0; j < TOPK; j++)
        if (sel[j] == e) {
          int p = atomicAdd(&ccnt, 1);
          ctok[p] = t; cwgt[p] = wj[j];
        }
    }
    __syncwarp();
  }
  __syncthreads();
  int n = ccnt;
  for (int m0 = 0; m0 < n; m0 += 32) {
    if (tid < 32) {
      int m = m0 + tid;
      ((int*)(sm+STOK))[tid]   = (m < n) ? ctok[m] : -1;
      ((float*)(sm+SWGT))[tid] = (m < n) ? cwgt[m] : 0.f;
    }
    __syncthreads();
    ffn_tile<true>(sm, x,
        Wg + (size_t)e*D_MODEL*D_HID, Wu + (size_t)e*D_MODEL*D_HID,
        Wd + (size_t)e*D_HID*D_MODEL, out, 0);
    __syncthreads();
  }
}

__global__ void k_aux(float* __restrict__ Out, int out_size) {
  if (out_size <= NTOK*D_MODEL) return;
  const float* reg = Out + (size_t)T0*D_MODEL;
  const int* cnt = (const int*)(reg + R_CNT);
  float sc = 0.f;
  for (int e = 0; e < NEXP; e++) sc += (float)cnt[e];
  float denom = fmaxf(sc, 1e-6f);
  float dot = 0.f;
  for (int e = 0; e < NEXP; e++)
    dot += ((float)cnt[e]/denom) * ((reg + R_PSUM)[e]/(float)NTOK);
  float Lbal = (float)NEXP * dot;
  float Lz = reg[R_LSE2] / (float)NTOK;
  float nr = (float)(*(const int*)(reg + R_NULL)) / (float)(NTOK*TOPK);
  float d = nr - 0.5f;
  Out[(size_t)NTOK*D_MODEL] = 0.02f*Lbal + 0.001f*Lz + 0.01f*d*d;
}

// ---------------- launch --------------------------------------------------------
extern "C" void kernel_launch(void* const* d_in, const int* in_sizes, int n_in,
                              void* d_out, int out_size) {
  const float* x     = (const float*)d_in[0];
  const float* gw    = (const float*)d_in[1];
  const float* bias  = (const float*)d_in[2];
  const float* nullp = (const float*)d_in[3];
  const float* Wg    = (const float*)d_in[4];
  const float* Wu    = (const float*)d_in[5];
  const float* Wd    = (const float*)d_in[6];
  const float* Wsg   = (const float*)d_in[7];
  const float* Wsu   = (const float*)d_in[8];
  const float* Wsd   = (const float*)d_in[9];
  float* out = (float*)d_out;
  float* reg = out + (size_t)T0*D_MODEL;

  cudaFuncSetAttribute(k_ffn_shared, cudaFuncAttributeMaxDynamicSharedMemorySize, SMEM_TOT);
  cudaFuncSetAttribute(k_ffn_routed, cudaFuncAttributeMaxDynamicSharedMemorySize, SMEM_TOT);
  cudaFuncSetAttribute(k_cleanup,    cudaFuncAttributeMaxDynamicSharedMemorySize, SMEM_TOT);

  k_zero_region<<<(R_END + 255)/256, 256>>>(reg);
  k_router<<<NTOK, 128>>>(x, gw, bias, nullp, reg);
  // main tokens [0, T0): shared base output, then routed atomicAdd
  k_ffn_shared<<<T0/32, 256, SMEM_TOT>>>(x, Wsg, Wsu, Wsd, out, 0);
  k_ffn_routed<<<dim3(CAPL/32, NEXP), 256, SMEM_TOT>>>(x, Wg, Wu, Wd, out, reg);
  // aux scalar (consumes region stats)
  k_aux<<<1, 1>>>(out, out_size);
  // tail tokens [T0, NTOK): shared pass overwrites metadata region with output,
  // then cleanup recomputes tail routing and adds routed contributions
  k_ffn_shared<<<NTAIL/32, 256, SMEM_TOT>>>(x, Wsg, Wsu, Wsd, out, T0);
  k_cleanup<<<NEXP, 256, SMEM_TOT>>>(x, gw, bias, nullp, Wg, Wu, Wd, out);
}

// round 15
// speedup vs baseline: 1.3671x; 1.3671x over previous
#include <cuda_runtime.h>
#include <cuda_bf16.h>
#include <math.h>
#include <cstdint>

#define D_MODEL 512
#define D_HID   1024
#define NTOK    4096
#define NEXP    64
#define TOPK    8
#define NNULL   64
#define T0      3840
#define NTAIL   (NTOK - T0)          // 256
#define CAPL    768

// metadata region (floats) at reg = out + T0*D_MODEL; overwritten by tail pass later
#define R_CNT   0
#define R_LLEN  64
#define R_PSUM  128
#define R_LSE2  192
#define R_NULL  193
#define R_TOK   256
#define R_WGT   (R_TOK + NEXP*CAPL)
#define R_END   (R_WGT + NEXP*CAPL)  // 98560 < 256*512

// dynamic smem layout (bytes)
#define SX(s,hl)    (((s)*2+(hl))*5120)                       // X: 2 slots x hi/lo, 64x32 stride 80
#define SW(mt,s,hl) (20480 + ((((mt)*2+(s))*2+(hl))*5120))    // W0/W1: 2 mats x 2 slots x hi/lo
#define SHH  61440                                            // h: 64x64 stride 144
#define SHL  70656
#define SW2H 79872                                            // W2: 32x512 (TR stride 1040) / 512x32 (stride 80)
#define SW2L 120832
#define STOK 161792
#define SWGT 162048
#define SMEM_TOT 162304

// ===================== PTX helpers ==============================================
__device__ __forceinline__ uint32_t smem_u32(const void* p) {
  uint32_t a;
  asm("{ .reg .u64 t; cvta.to.shared.u64 t, %1; cvt.u32.u64 %0, t; }" : "=r"(a) : "l"(p));
  return a;
}
#define LDSM4(r, a) \
  asm volatile("ldmatrix.sync.aligned.m8n8.x4.shared.b16 {%0,%1,%2,%3}, [%4];" \
    : "=r"((r)[0]), "=r"((r)[1]), "=r"((r)[2]), "=r"((r)[3]) : "r"(a))
#define LDSM2(r, a) \
  asm volatile("ldmatrix.sync.aligned.m8n8.x2.shared.b16 {%0,%1}, [%2];" \
    : "=r"((r)[0]), "=r"((r)[1]) : "r"(a))
#define LDSM2T(r, a) \
  asm volatile("ldmatrix.sync.aligned.m8n8.x2.trans.shared.b16 {%0,%1}, [%2];" \
    : "=r"((r)[0]), "=r"((r)[1]) : "r"(a))
#define MMA16816(c, a, b) \
  asm volatile("mma.sync.aligned.m16n8k16.row.col.f32.bf16.bf16.f32 " \
    "{%0,%1,%2,%3}, {%4,%5,%6,%7}, {%8,%9}, {%0,%1,%2,%3};" \
    : "+f"((c)[0]), "+f"((c)[1]), "+f"((c)[2]), "+f"((c)[3]) \
    : "r"((a)[0]), "r"((a)[1]), "r"((a)[2]), "r"((a)[3]), "r"((b)[0]), "r"((b)[1]))

__device__ __forceinline__ void split2(float v, __nv_bfloat16& h, __nv_bfloat16& l) {
  h = __float2bfloat16_rn(v);
  l = __float2bfloat16_rn(v - __bfloat162float(h));
}
__device__ __forceinline__ void split_store(char* bh, char* bl, uint32_t off, float4 v) {
  __nv_bfloat16 h0,l0,h1,l1,h2,l2,h3,l3;
  split2(v.x,h0,l0); split2(v.y,h1,l1); split2(v.z,h2,l2); split2(v.w,h3,l3);
  *(__nv_bfloat162*)(bh + off)     = __halves2bfloat162(h0,h1);
  *(__nv_bfloat162*)(bh + off + 4) = __halves2bfloat162(h2,h3);
  *(__nv_bfloat162*)(bl + off)     = __halves2bfloat162(l0,l1);
  *(__nv_bfloat162*)(bl + off + 4) = __halves2bfloat162(l2,l3);
}
__device__ __forceinline__ float siluf(float v) { return v / (1.f + __expf(-v)); }

__device__ void top8(const float* lg, float nv, int* sel, float* wout, int* nnull) {
  unsigned long long used = 0ull;
  float sl[TOPK]; int nn = 0;
  for (int j = 0; j < TOPK; j++) {
    float best = -1e30f; int bi = -1;
    for (int e = 0; e < NEXP; e++)
      if (!((used >> e) & 1ull) && lg[e] > best) { best = lg[e]; bi = e; }
    if (nv > best) { sel[j] = -1; sl[j] = nv; nn++; }
    else           { sel[j] = bi; sl[j] = best; used |= (1ull << bi); }
  }
  float m = -1e30f;
  for (int j = 0; j < TOPK; j++) if (sel[j] >= 0 && sl[j] > m) m = sl[j];
  float ss = 0.f;
  for (int j = 0; j < TOPK; j++) { wout[j] = (sel[j] >= 0) ? __expf(sl[j]-m) : 0.f; ss += wout[j]; }
  float inv = (ss > 1e-30f) ? 1.f/ss : 0.f;
  for (int j = 0; j < TOPK; j++) wout[j] *= inv;
  *nnull = nn;
}

// ===================== fused FFN tile: 64 tokens x full D_MODEL =================
// TR=true : routed — W0/W1 [D][H] k-major, W2 [H][D] k-major; rows from smem list;
//           weighted atomicAdd into out.
// TR=false: shared — W0/W1 [H][D] n-major, W2 [D][H] n-major; rows mbase+..; stores.
template<bool TR>
__device__ void ffn_tile(char* sm, const float* __restrict__ x,
    const float* __restrict__ W0, const float* __restrict__ W1,
    const float* __restrict__ W2, float* __restrict__ out, int mbase) {
  int tid = threadIdx.x, lane = tid & 31, wid = tid >> 5;
  uint32_t smb = smem_u32(sm);
  const int*   stok = (const int*)(sm + STOK);
  const float* swgt = (const float*)(sm + SWGT);
  int wm1 = (wid & 1)*32, wn1 = (wid >> 1)*16;    // stage1: 64x64, warp 32x16
  int wm2 = (wid & 1)*32, wn2 = (wid >> 1)*128;   // stage2: 64x512, warp 32x128

  float acc2[2][16][4];
  #pragma unroll
  for (int i = 0; i < 2; i++)
    #pragma unroll
    for (int j = 0; j < 16; j++)
      #pragma unroll
      for (int q = 0; q < 4; q++) acc2[i][j][q] = 0.f;

  for (int hc = 0; hc < D_HID/64; hc++) {
    float acc1[2][2][2][4];   // [mat][i][j][4]
    #pragma unroll
    for (int mt = 0; mt < 2; mt++)
      #pragma unroll
      for (int i = 0; i < 2; i++)
        #pragma unroll
        for (int j = 0; j < 2; j++)
          #pragma unroll
          for (int q = 0; q < 4; q++) acc1[mt][i][j][q] = 0.f;

    for (int kp = 0; kp < 8; kp++) {
      __syncthreads();
      #pragma unroll
      for (int s = 0; s < 2; s++) {
        int kc = kp*2 + s;
        { // X tile 64x32
          #pragma unroll
          for (int it = 0; it < 2; it++) {
            int idx = tid + it*256;
            int row = idx >> 3, c4 = idx & 7;
            float4 v = make_float4(0.f,0.f,0.f,0.f);
            int tok = TR ? stok[row] : (mbase + row);
            if (!TR || tok >= 0)
              v = *(const float4*)(x + (size_t)tok*D_MODEL + kc*32 + c4*4);
            split_store(sm+SX(s,0), sm+SX(s,1), (uint32_t)row*80 + c4*8, v);
          }
        }
        #pragma unroll
        for (int mt = 0; mt < 2; mt++) {
          const float* W = mt ? W1 : W0;
          char* bh = sm + SW(mt,s,0); char* bl = sm + SW(mt,s,1);
          if (TR) {   // 32k x 64n, stride 144
            #pragma unroll
            for (int it = 0; it < 2; it++) {
              int idx = tid + it*256;
              int row = idx >> 4, c4 = idx & 15;
              float4 v = *(const float4*)(W + (size_t)(kc*32+row)*D_HID + hc*64 + c4*4);
              split_store(bh, bl, (uint32_t)row*144 + c4*8, v);
            }
          } else {    // 64n x 32k, stride 80
            #pragma unroll
            for (int it = 0; it < 2; it++) {
              int idx = tid + it*256;
              int row = idx >> 3, c4 = idx & 7;
              float4 v = *(const float4*)(W + (size_t)(hc*64+row)*D_MODEL + kc*32 + c4*4);
              split_store(bh, bl, (uint32_t)row*80 + c4*8, v);
            }
          }
        }
      }
      __syncthreads();
      #pragma unroll
      for (int s = 0; s < 2; s++) {
        #pragma unroll
        for (int ks = 0; ks < 2; ks++) {
          uint32_t ah[2][4], al[2][4];
          #pragma unroll
          for (int i = 0; i < 2; i++) {
            uint32_t ao = (uint32_t)(wm1 + i*16 + (lane & 15))*80 + (ks*16 + (lane >> 4)*8)*2;
            LDSM4(ah[i], smb+SX(s,0)+ao); LDSM4(al[i], smb+SX(s,1)+ao);
          }
          #pragma unroll
          for (int mt = 0; mt < 2; mt++) {
            #pragma unroll
            for (int j = 0; j < 2; j++) {
              uint32_t bh[2], bl2[2];
              if (TR) {
                uint32_t bb = (uint32_t)(ks*16 + (lane & 15))*144 + (wn1 + j*8)*2;
                LDSM2T(bh, smb+SW(mt,s,0)+bb); LDSM2T(bl2, smb+SW(mt,s,1)+bb);
              } else {
                uint32_t bb = (uint32_t)(wn1 + j*8 + (lane & 7))*80 + (ks*16 + ((lane >> 3) & 1)*8)*2;
                LDSM2(bh, smb+SW(mt,s,0)+bb); LDSM2(bl2, smb+SW(mt,s,1)+bb);
              }
              #pragma unroll
              for (int i = 0; i < 2; i++) {
                MMA16816(acc1[mt][i][j], ah[i], bh);
                MMA16816(acc1[mt][i][j], ah[i], bl2);
                MMA16816(acc1[mt][i][j], al[i], bh);
              }
            }
          }
        }
      }
    }
    // h = silu(gate)*up -> smem (64x64, stride 144). Safe without sync: previous
    // hc's stage2 readers finished before this hc's first kp barrier.
    { int r = lane >> 2, c = (lane & 3)*2;
      #pragma unroll
      for (int i = 0; i < 2; i++)
        #pragma unroll
        for (int j = 0; j < 2; j++)
          #pragma unroll
          for (int half = 0; half < 2; half++) {
            int row = wm1 + i*16 + r + half*8;
            float h0 = siluf(acc1[0][i][j][half*2+0]) * acc1[1][i][j][half*2+0];
            float h1 = siluf(acc1[0][i][j][half*2+1]) * acc1[1][i][j][half*2+1];
            __nv_bfloat16 hh0,hl0,hh1,hl1;
            split2(h0,hh0,hl0); split2(h1,hh1,hl1);
            uint32_t off = (uint32_t)row*144 + (wn1 + j*8 + c)*2;
            *(__nv_bfloat162*)(sm+SHH+off) = __halves2bfloat162(hh0,hh1);
            *(__nv_bfloat162*)(sm+SHL+off) = __halves2bfloat162(hl0,hl1);
          } }
    // stage2: consume h in two 32-k sub-chunks
    #pragma unroll
    for (int hk = 0; hk < 2; hk++) {
      __syncthreads();
      if (TR) {      // W2 chunk 32k x 512n, stride 1040
        #pragma unroll
        for (int it = 0; it < 16; it++) {
          int idx = tid + it*256;
          int row = idx >> 7, c4 = idx & 127;
          float4 v = *(const float4*)(W2 + (size_t)(hc*64 + hk*32 + row)*D_MODEL + c4*4);
          split_store(sm+SW2H, sm+SW2L, (uint32_t)row*1040 + c4*8, v);
        }
      } else {       // 512n x 32k, stride 80
        #pragma unroll
        for (int it = 0; it < 16; it++) {
          int idx = tid + it*256;
          int row = idx >> 3, c4 = idx & 7;
          float4 v = *(const float4*)(W2 + (size_t)row*D_HID + hc*64 + hk*32 + c4*4);
          split_store(sm+SW2H, sm+SW2L, (uint32_t)row*80 + c4*8, v);
        }
      }
      __syncthreads();
      #pragma unroll
      for (int ks = 0; ks < 2; ks++) {
        uint32_t ah[2][4], al[2][4];
        #pragma unroll
        for (int i = 0; i < 2; i++) {
          uint32_t ao = (uint32_t)(wm2 + i*16 + (lane & 15))*144 + (hk*32 + ks*16 + (lane >> 4)*8)*2;
          LDSM4(ah[i], smb+SHH+ao); LDSM4(al[i], smb+SHL+ao);
        }
        #pragma unroll
        for (int j = 0; j < 16; j++) {
          uint32_t bh[2], bl2[2];
          if (TR) {
            uint32_t bb = (uint32_t)(ks*16 + (lane & 15))*1040 + (wn2 + j*8)*2;
            LDSM2T(bh, smb+SW2H+bb); LDSM2T(bl2, smb+SW2L+bb);
          } else {
            uint32_t bb = (uint32_t)(wn2 + j*8 + (lane & 7))*80 + (ks*16 + ((lane >> 3) & 1)*8)*2;
            LDSM2(bh, smb+SW2H+bb); LDSM2(bl2, smb+SW2L+bb);
          }
          #pragma unroll
          for (int i = 0; i < 2; i++) {
            MMA16816(acc2[i][j], ah[i], bh);
            MMA16816(acc2[i][j], ah[i], bl2);
            MMA16816(acc2[i][j], al[i], bh);
          }
        }
      }
    }
  }
  // epilogue
  int r = lane >> 2, c = (lane & 3)*2;
  #pragma unroll
  for (int i = 0; i < 2; i++)
    #pragma unroll
    for (int half = 0; half < 2; half++) {
      int rl = wm2 + i*16 + r + half*8;
      if (TR) {
        int tok = stok[rl];
        if (tok < 0) continue;
        float w = swgt[rl];
        float* dst = out + (size_t)tok*D_MODEL;
        #pragma unroll
        for (int j = 0; j < 16; j++) {
          int col = wn2 + j*8 + c;
          atomicAdd(dst + col,     acc2[i][j][half*2+0]*w);
          atomicAdd(dst + col + 1, acc2[i][j][half*2+1]*w);
        }
      } else {
        float* dst = out + (size_t)(mbase + rl)*D_MODEL;
        #pragma unroll
        for (int j = 0; j < 16; j++) {
          int col = wn2 + j*8 + c;
          *(float2*)(dst + col) = make_float2(acc2[i][j][half*2+0], acc2[i][j][half*2+1]);
        }
      }
    }
}

// ===================== kernels ==================================================
__global__ void k_zero_region(float* __restrict__ reg) {
  int i = blockIdx.x*256 + threadIdx.x;
  if (i < R_END) reg[i] = 0.f;
}

__global__ __launch_bounds__(128) void k_router(const float* __restrict__ x,
    const float* __restrict__ gw, const float* __restrict__ bias,
    const float* __restrict__ nullp, float* __restrict__ reg) {
  __shared__ float xs[D_MODEL];
  __shared__ float lg[NEXP];
  int t = blockIdx.x, tid = threadIdx.x;
  *(float4*)(xs + tid*4) = *(const float4*)(x + (size_t)t*D_MODEL + tid*4);
  __syncthreads();
  if (tid < NEXP) {
    const float* w = gw + (size_t)tid*D_MODEL;
    float s = 0.f;
    #pragma unroll 8
    for (int k = 0; k < D_MODEL; k += 4) {
      float4 wv = *(const float4*)(w + k);
      s += xs[k]*wv.x + xs[k+1]*wv.y + xs[k+2]*wv.z + xs[k+3]*wv.w;
    }
    lg[tid] = s + bias[tid];
  }
  __syncthreads();
  if (tid == 0) {
    int*   cnt  = (int*)(reg + R_CNT);
    int*   llen = (int*)(reg + R_LLEN);
    float* psum = reg + R_PSUM;
    int*   ltok = (int*)(reg + R_TOK);
    float* lwgt = reg + R_WGT;
    float nv = *nullp;
    int sel[TOPK]; float wj[TOPK]; int nn;
    top8(lg, nv, sel, wj, &nn);
    for (int j = 0; j < TOPK; j++) {
      if (sel[j] >= 0) {
        atomicAdd(&cnt[sel[j]], 1);
        if (t < T0) {
          int pos = atomicAdd(&llen[sel[j]], 1);
          if (pos < CAPL) {
            ltok[sel[j]*CAPL + pos] = t;
            lwgt[sel[j]*CAPL + pos] = wj[j];
          }
        }
      }
    }
    if (nn) atomicAdd((int*)(reg + R_NULL), nn);
    float mr = -1e30f;
    for (int e = 0; e < NEXP; e++) if (lg[e] > mr) mr = lg[e];
    float Z = 0.f;
    for (int e = 0; e < NEXP; e++) Z += __expf(lg[e]-mr);
    float invZ = 1.f/Z;
    for (int e = 0; e < NEXP; e++) atomicAdd(&psum[e], __expf(lg[e]-mr)*invZ);
    float m2 = fmaxf(mr, nv);
    float Z2 = Z*__expf(mr-m2) + (float)NNULL*__expf(nv-m2);
    float lse = m2 + logf(Z2);
    atomicAdd(reg + R_LSE2, lse*lse);
  }
}

__global__ __launch_bounds__(256) void k_ffn_shared(const float* __restrict__ x,
    const float* __restrict__ Wsg, const float* __restrict__ Wsu,
    const float* __restrict__ Wsd, float* __restrict__ out, int mb) {
  extern __shared__ char sm[];
  ffn_tile<false>(sm, x, Wsg, Wsu, Wsd, out, mb + blockIdx.x*64);
}

__global__ __launch_bounds__(256) void k_ffn_routed(const float* __restrict__ x,
    const float* __restrict__ Wg, const float* __restrict__ Wu,
    const float* __restrict__ Wd, float* __restrict__ out,
    const float* __restrict__ reg) {
  extern __shared__ char sm[];
  int e = blockIdx.y;
  int len = min(((const int*)(reg + R_LLEN))[e], CAPL);
  int m0 = blockIdx.x*64;
  if (m0 >= len) return;
  if (threadIdx.x < 64) {
    int m = m0 + threadIdx.x;
    ((int*)(sm+STOK))[threadIdx.x]   = (m < len) ? ((const int*)(reg + R_TOK))[e*CAPL + m] : -1;
    ((float*)(sm+SWGT))[threadIdx.x] = (m < len) ? (reg + R_WGT)[e*CAPL + m] : 0.f;
  }
  __syncthreads();
  ffn_tile<true>(sm, x,
      Wg + (size_t)e*D_MODEL*D_HID, Wu + (size_t)e*D_MODEL*D_HID,
      Wd + (size_t)e*D_HID*D_MODEL, out, 0);
}

// one block per expert: recompute tail-token routing, run routed FFN on them
__global__ __launch_bounds__(256) void k_cleanup(const float* __restrict__ x,
    const float* __restrict__ gw, const float* __restrict__ bias,
    const float* __restrict__ nullp,
    const float* __restrict__ Wg, const float* __restrict__ Wu,
    const float* __restrict__ Wd, float* __restrict__ out) {
  extern __shared__ char sm[];
  __shared__ float clg[8][NEXP];
  __shared__ int   ctok[NTAIL];
  __shared__ float cwgt[NTAIL];
  __shared__ int   ccnt;
  int tid = threadIdx.x, lane = tid & 31, wid = tid >> 5;
  int e = blockIdx.x;
  if (tid == 0) ccnt = 0;
  __syncthreads();
  float nv = *nullp;
  for (int ti = wid; ti < NTAIL; ti += 8) {
    int t = T0 + ti;
    const float4* xr = (const float4*)(x + (size_t)t*D_MODEL);
    #pragma unroll
    for (int sub = 0; sub < 2; sub++) {
      int e2 = lane + sub*32;
      const float4* wr = (const float4*)(gw + (size_t)e2*D_MODEL);
      float s = 0.f;
      #pragma unroll 8
      for (int k = 0; k < D_MODEL/4; k++) {
        float4 a = xr[k], b = wr[k];
        s += a.x*b.x + a.y*b.y + a.z*b.z + a.w*b.w;
      }
      clg[wid][e2] = s + bias[e2];
    }
    __syncwarp();
    if (lane == 0) {
      int sel[TOPK]; float wj[TOPK]; int nn;
      top8(clg[wid], nv, sel, wj, &nn);
      for (int j = 0; j < TOPK; j++)
        if (sel[j] == e) {
          int p = atomicAdd(&ccnt, 1);
          ctok[p] = t; cwgt[p] = wj[j];
        }
    }
    __syncwarp();
  }
  __syncthreads();
  int n = ccnt;
  for (int m0 = 0; m0 < n; m0 += 64) {
    if (tid < 64) {
      int m = m0 + tid;
      ((int*)(sm+STOK))[tid]   = (m < n) ? ctok[m] : -1;
      ((float*)(sm+SWGT))[tid] = (m < n) ? cwgt[m] : 0.f;
    }
    __syncthreads();
    ffn_tile<true>(sm, x,
        Wg + (size_t)e*D_MODEL*D_HID, Wu + (size_t)e*D_MODEL*D_HID,
        Wd + (size_t)e*D_HID*D_MODEL, out, 0);
    __syncthreads();
  }
}

__global__ void k_aux(float* __restrict__ Out, int out_size) {
  if (out_size <= NTOK*D_MODEL) return;
  const float* reg = Out + (size_t)T0*D_MODEL;
  const int* cnt = (const int*)(reg + R_CNT);
  float sc = 0.f;
  for (int e = 0; e < NEXP; e++) sc += (float)cnt[e];
  float denom = fmaxf(sc, 1e-6f);
  float dot = 0.f;
  for (int e = 0; e < NEXP; e++)
    dot += ((float)cnt[e]/denom) * ((reg + R_PSUM)[e]/(float)NTOK);
  float Lbal = (float)NEXP * dot;
  float Lz = reg[R_LSE2] / (float)NTOK;
  float nr = (float)(*(const int*)(reg + R_NULL)) / (float)(NTOK*TOPK);
  float d = nr - 0.5f;
  Out[(size_t)NTOK*D_MODEL] = 0.02f*Lbal + 0.001f*Lz + 0.01f*d*d;
}

// ---------------- launch --------------------------------------------------------
extern "C" void kernel_launch(void* const* d_in, const int* in_sizes, int n_in,
                              void* d_out, int out_size) {
  const float* x     = (const float*)d_in[0];
  const float* gw    = (const float*)d_in[1];
  const float* bias  = (const float*)d_in[2];
  const float* nullp = (const float*)d_in[3];
  const float* Wg    = (const float*)d_in[4];
  const float* Wu    = (const float*)d_in[5];
  const float* Wd    = (const float*)d_in[6];
  const float* Wsg   = (const float*)d_in[7];
  const float* Wsu   = (const float*)d_in[8];
  const float* Wsd   = (const float*)d_in[9];
  float* out = (float*)d_out;
  float* reg = out + (size_t)T0*D_MODEL;

  cudaFuncSetAttribute(k_ffn_shared, cudaFuncAttributeMaxDynamicSharedMemorySize, SMEM_TOT);
  cudaFuncSetAttribute(k_ffn_routed, cudaFuncAttributeMaxDynamicSharedMemorySize, SMEM_TOT);
  cudaFuncSetAttribute(k_cleanup,    cudaFuncAttributeMaxDynamicSharedMemorySize, SMEM_TOT);

  k_zero_region<<<(R_END + 255)/256, 256>>>(reg);
  k_router<<<NTOK, 128>>>(x, gw, bias, nullp, reg);
  // main tokens [0, T0): shared base output, then routed atomicAdd
  k_ffn_shared<<<T0/64, 256, SMEM_TOT>>>(x, Wsg, Wsu, Wsd, out, 0);
  k_ffn_routed<<<dim3(CAPL/64, NEXP), 256, SMEM_TOT>>>(x, Wg, Wu, Wd, out, reg);
  // aux scalar (consumes region stats)
  k_aux<<<1, 1>>>(out, out_size);
  // tail tokens [T0, NTOK): shared pass overwrites metadata region with output,
  // then cleanup recomputes tail routing and adds routed contributions
  k_ffn_shared<<<NTAIL/64, 256, SMEM_TOT>>>(x, Wsg, Wsu, Wsd, out, T0);
  k_cleanup<<<NEXP, 256, SMEM_TOT>>>(x, gw, bias, nullp, Wg, Wu, Wd, out);
}

// round 16
// speedup vs baseline: 1.6269x; 1.1901x over previous
#include <cuda_runtime.h>
#include <cuda_fp16.h>
#include <math.h>
#include <cstdint>

#define D_MODEL 512
#define D_HID   1024
#define NTOK    4096
#define NEXP    64
#define TOPK    8
#define NNULL   64
#define T0      3840
#define NTAIL   (NTOK - T0)          // 256
#define CAPL    768

// metadata region (floats) at reg = out + T0*D_MODEL; overwritten by tail pass later
#define R_CNT   0
#define R_LLEN  64
#define R_PSUM  128
#define R_LSE2  192
#define R_NULL  193
#define R_TOK   256
#define R_WGT   (R_TOK + NEXP*CAPL)
#define R_END   (R_WGT + NEXP*CAPL)  // 98560 < 256*512

// dynamic smem layout (bytes)
#define XSTG(s)    ((s)*8192)                      // fp32 staging: X 64x32
#define WSTG(mt,s) (16384 + ((mt)*2+(s))*8192)     // fp32 staging: W0/W1 32x64 or 64x32
#define SXH  49152                                 // X hi: 64x32 fp16, stride 80
#define SXL  54272                                 // X lo
#define SW0H 59392                                 // W0 hi (TR: 32x64 stride 144; else 64x32 stride 80)
#define SW1H 64512
#define SHH  69632                                 // h hi: 64x64 fp16, stride 144
#define SHL  78848
#define SW2H 88064                                 // W2 hi: TR 64x512 stride 1040 (66560); else 512x64 stride 144 (73728)
#define STOK 161792
#define SWGT 162048
#define SMEM_TOT 162304

// ===================== PTX helpers ==============================================
__device__ __forceinline__ uint32_t smem_u32(const void* p) {
  uint32_t a;
  asm("{ .reg .u64 t; cvta.to.shared.u64 t, %1; cvt.u32.u64 %0, t; }" : "=r"(a) : "l"(p));
  return a;
}
#define CP_ASYNC16(s, g) \
  asm volatile("cp.async.cg.shared.global [%0], [%1], 16;" :: "r"(s), "l"(g))
#define CP_COMMIT() asm volatile("cp.async.commit_group;" ::: "memory")
#define CP_WAIT1()  asm volatile("cp.async.wait_group 1;" ::: "memory")
#define LDSM4(r, a) \
  asm volatile("ldmatrix.sync.aligned.m8n8.x4.shared.b16 {%0,%1,%2,%3}, [%4];" \
    : "=r"((r)[0]), "=r"((r)[1]), "=r"((r)[2]), "=r"((r)[3]) : "r"(a))
#define LDSM2(r, a) \
  asm volatile("ldmatrix.sync.aligned.m8n8.x2.shared.b16 {%0,%1}, [%2];" \
    : "=r"((r)[0]), "=r"((r)[1]) : "r"(a))
#define LDSM2T(r, a) \
  asm volatile("ldmatrix.sync.aligned.m8n8.x2.trans.shared.b16 {%0,%1}, [%2];" \
    : "=r"((r)[0]), "=r"((r)[1]) : "r"(a))
#define MMAH(c, a, b) \
  asm volatile("mma.sync.aligned.m16n8k16.row.col.f32.f16.f16.f32 " \
    "{%0,%1,%2,%3}, {%4,%5,%6,%7}, {%8,%9}, {%0,%1,%2,%3};" \
    : "+f"((c)[0]), "+f"((c)[1]), "+f"((c)[2]), "+f"((c)[3]) \
    : "r"((a)[0]), "r"((a)[1]), "r"((a)[2]), "r"((a)[3]), "r"((b)[0]), "r"((b)[1]))

__device__ __forceinline__ void split2h(float v, __half& h, __half& l) {
  h = __float2half_rn(v);
  l = __float2half_rn(v - __half2float(h));
}
__device__ __forceinline__ void split_store2(char* bh, char* bl, uint32_t off, float4 v) {
  __half h0,l0,h1,l1,h2,l2,h3,l3;
  split2h(v.x,h0,l0); split2h(v.y,h1,l1); split2h(v.z,h2,l2); split2h(v.w,h3,l3);
  *(__half2*)(bh + off)     = __halves2half2(h0,h1);
  *(__half2*)(bh + off + 4) = __halves2half2(h2,h3);
  *(__half2*)(bl + off)     = __halves2half2(l0,l1);
  *(__half2*)(bl + off + 4) = __halves2half2(l2,l3);
}
__device__ __forceinline__ void store_hi(char* b, uint32_t off, float4 v) {
  *(__half2*)(b + off)     = __floats2half2_rn(v.x, v.y);
  *(__half2*)(b + off + 4) = __floats2half2_rn(v.z, v.w);
}
__device__ __forceinline__ float siluf(float v) { return v / (1.f + __expf(-v)); }

__device__ void top8(const float* lg, float nv, int* sel, float* wout, int* nnull) {
  unsigned long long used = 0ull;
  float sl[TOPK]; int nn = 0;
  for (int j = 0; j < TOPK; j++) {
    float best = -1e30f; int bi = -1;
    for (int e = 0; e < NEXP; e++)
      if (!((used >> e) & 1ull) && lg[e] > best) { best = lg[e]; bi = e; }
    if (nv > best) { sel[j] = -1; sl[j] = nv; nn++; }
    else           { sel[j] = bi; sl[j] = best; used |= (1ull << bi); }
  }
  float m = -1e30f;
  for (int j = 0; j < TOPK; j++) if (sel[j] >= 0 && sl[j] > m) m = sl[j];
  float ss = 0.f;
  for (int j = 0; j < TOPK; j++) { wout[j] = (sel[j] >= 0) ? __expf(sl[j]-m) : 0.f; ss += wout[j]; }
  float inv = (ss > 1e-30f) ? 1.f/ss : 0.f;
  for (int j = 0; j < TOPK; j++) wout[j] *= inv;
  *nnull = nn;
}

// ===================== fused FFN tile: 64 tokens x full D_MODEL =================
// fp16 2-MMA: A (X, h) split hi+lo, B (weights) hi only.
// TR=true : routed — W0/W1 [D][H] k-major, W2 [H][D] k-major; token list in smem;
//           weighted atomicAdd. TR=false: shared — n-major weights; plain stores.
template<bool TR>
__device__ void ffn_tile(char* sm, const float* __restrict__ x,
    const float* __restrict__ W0, const float* __restrict__ W1,
    const float* __restrict__ W2, float* __restrict__ out, int mbase) {
  int tid = threadIdx.x, lane = tid & 31, wid = tid >> 5;
  uint32_t smb = smem_u32(sm);
  const int*   stok = (const int*)(sm + STOK);
  const float* swgt = (const float*)(sm + SWGT);
  int wm1 = (wid & 1)*32, wn1 = (wid >> 1)*16;    // stage1 64x64, warp 32x16
  int wm2 = (wid & 1)*32, wn2 = (wid >> 1)*128;   // stage2 64x512, warp 32x128

  float acc2[2][16][4];
  #pragma unroll
  for (int i = 0; i < 2; i++)
    #pragma unroll
    for (int j = 0; j < 16; j++)
      #pragma unroll
      for (int q = 0; q < 4; q++) acc2[i][j][q] = 0.f;

  for (int hc = 0; hc < D_HID/64; hc++) {
    float acc1[2][2][2][4];
    #pragma unroll
    for (int mt = 0; mt < 2; mt++)
      #pragma unroll
      for (int i = 0; i < 2; i++)
        #pragma unroll
        for (int j = 0; j < 2; j++)
          #pragma unroll
          for (int q = 0; q < 4; q++) acc1[mt][i][j][q] = 0.f;

    // ---- stage 1: gate/up over K=512 in 16 chunks of 32, cp.async pipelined ----
    {
      // prologue: stage chunk 0
      #pragma unroll
      for (int it = 0; it < 2; it++) {
        int idx = tid + it*256, row = idx >> 3, c4 = idx & 7;
        int tk = TR ? stok[row] : (mbase + row);
        if (TR && tk < 0) tk = 0;
        CP_ASYNC16(smb + XSTG(0) + row*128 + c4*16,
                   x + (size_t)tk*D_MODEL + 0*32 + c4*4);
      }
      #pragma unroll
      for (int mt = 0; mt < 2; mt++) {
        const float* W = mt ? W1 : W0;
        #pragma unroll
        for (int it = 0; it < 2; it++) {
          int idx = tid + it*256;
          if (TR) {
            int row = idx >> 4, c4 = idx & 15;
            CP_ASYNC16(smb + WSTG(mt,0) + row*256 + c4*16,
                       W + (size_t)(0*32+row)*D_HID + hc*64 + c4*4);
          } else {
            int row = idx >> 3, c4 = idx & 7;
            CP_ASYNC16(smb + WSTG(mt,0) + row*128 + c4*16,
                       W + (size_t)(hc*64+row)*D_MODEL + 0*32 + c4*4);
          }
        }
      }
      CP_COMMIT();
    }
    for (int kc = 0; kc < 16; kc++) {
      if (kc + 1 < 16) {
        int kn = kc + 1, s = kn & 1;
        #pragma unroll
        for (int it = 0; it < 2; it++) {
          int idx = tid + it*256, row = idx >> 3, c4 = idx & 7;
          int tk = TR ? stok[row] : (mbase + row);
          if (TR && tk < 0) tk = 0;
          CP_ASYNC16(smb + XSTG(s) + row*128 + c4*16,
                     x + (size_t)tk*D_MODEL + kn*32 + c4*4);
        }
        #pragma unroll
        for (int mt = 0; mt < 2; mt++) {
          const float* W = mt ? W1 : W0;
          #pragma unroll
          for (int it = 0; it < 2; it++) {
            int idx = tid + it*256;
            if (TR) {
              int row = idx >> 4, c4 = idx & 15;
              CP_ASYNC16(smb + WSTG(mt,s) + row*256 + c4*16,
                         W + (size_t)(kn*32+row)*D_HID + hc*64 + c4*4);
            } else {
              int row = idx >> 3, c4 = idx & 7;
              CP_ASYNC16(smb + WSTG(mt,s) + row*128 + c4*16,
                         W + (size_t)(hc*64+row)*D_MODEL + kn*32 + c4*4);
            }
          }
        }
      }
      CP_COMMIT();
      CP_WAIT1();
      __syncthreads();
      // convert staged chunk kc -> fp16 operands
      {
        int s = kc & 1;
        #pragma unroll
        for (int it = 0; it < 2; it++) {
          int idx = tid + it*256, row = idx >> 3, c4 = idx & 7;
          float4 v = *(const float4*)(sm + XSTG(s) + row*128 + c4*16);
          split_store2(sm+SXH, sm+SXL, (uint32_t)row*80 + c4*8, v);
        }
        #pragma unroll
        for (int mt = 0; mt < 2; mt++) {
          char* bdst = sm + (mt ? SW1H : SW0H);
          #pragma unroll
          for (int it = 0; it < 2; it++) {
            int idx = tid + it*256;
            if (TR) {
              int row = idx >> 4, c4 = idx & 15;
              float4 v = *(const float4*)(sm + WSTG(mt,s) + row*256 + c4*16);
              store_hi(bdst, (uint32_t)row*144 + c4*8, v);
            } else {
              int row = idx >> 3, c4 = idx & 7;
              float4 v = *(const float4*)(sm + WSTG(mt,s) + row*128 + c4*16);
              store_hi(bdst, (uint32_t)row*80 + c4*8, v);
            }
          }
        }
      }
      __syncthreads();
      // MMA on chunk kc
      #pragma unroll
      for (int ks = 0; ks < 2; ks++) {
        uint32_t ah[2][4], al[2][4];
        #pragma unroll
        for (int i = 0; i < 2; i++) {
          uint32_t ao = (uint32_t)(wm1 + i*16 + (lane & 15))*80 + (ks*16 + (lane >> 4)*8)*2;
          LDSM4(ah[i], smb+SXH+ao); LDSM4(al[i], smb+SXL+ao);
        }
        #pragma unroll
        for (int mt = 0; mt < 2; mt++) {
          uint32_t ubh = smb + (mt ? SW1H : SW0H);
          #pragma unroll
          for (int j = 0; j < 2; j++) {
            uint32_t bh[2];
            if (TR) {
              uint32_t bb = (uint32_t)(ks*16 + (lane & 15))*144 + (wn1 + j*8)*2;
              LDSM2T(bh, ubh+bb);
            } else {
              uint32_t bb = (uint32_t)(wn1 + j*8 + (lane & 7))*80 + (ks*16 + ((lane >> 3) & 1)*8)*2;
              LDSM2(bh, ubh+bb);
            }
            #pragma unroll
            for (int i = 0; i < 2; i++) {
              MMAH(acc1[mt][i][j], ah[i], bh);
              MMAH(acc1[mt][i][j], al[i], bh);
            }
          }
        }
      }
    }
    // h = silu(gate)*up -> smem fp16 hi/lo (64x64, stride 144); barrier-safe:
    // all warps passed the last chunk's post-convert barrier.
    { int r = lane >> 2, c = (lane & 3)*2;
      #pragma unroll
      for (int i = 0; i < 2; i++)
        #pragma unroll
        for (int j = 0; j < 2; j++)
          #pragma unroll
          for (int half = 0; half < 2; half++) {
            int row = wm1 + i*16 + r + half*8;
            float h0 = siluf(acc1[0][i][j][half*2+0]) * acc1[1][i][j][half*2+0];
            float h1 = siluf(acc1[0][i][j][half*2+1]) * acc1[1][i][j][half*2+1];
            __half hh0,hl0,hh1,hl1;
            split2h(h0,hh0,hl0); split2h(h1,hh1,hl1);
            uint32_t off = (uint32_t)row*144 + (wn1 + j*8 + c)*2;
            *(__half2*)(sm+SHH+off) = __halves2half2(hh0,hh1);
            *(__half2*)(sm+SHL+off) = __halves2half2(hl0,hl1);
          } }
    // ---- stage 2: down over this hc's 64 h-cols ----
    __syncthreads();
    #pragma unroll
    for (int it = 0; it < 32; it++) {
      int idx = tid + it*256;
      if (TR) {
        int row = idx >> 7, c4 = idx & 127;     // 64 k-rows x 512 n, stride 1040
        float4 v = *(const float4*)(W2 + (size_t)(hc*64+row)*D_MODEL + c4*4);
        store_hi(sm+SW2H, (uint32_t)row*1040 + c4*8, v);
      } else {
        int row = idx >> 4, c4 = idx & 15;      // 512 n-rows x 64 k, stride 144
        float4 v = *(const float4*)(W2 + (size_t)row*D_HID + hc*64 + c4*4);
        store_hi(sm+SW2H, (uint32_t)row*144 + c4*8, v);
      }
    }
    __syncthreads();
    #pragma unroll
    for (int ks = 0; ks < 4; ks++) {
      uint32_t ah[2][4], al[2][4];
      #pragma unroll
      for (int i = 0; i < 2; i++) {
        uint32_t ao = (uint32_t)(wm2 + i*16 + (lane & 15))*144 + (ks*16 + (lane >> 4)*8)*2;
        LDSM4(ah[i], smb+SHH+ao); LDSM4(al[i], smb+SHL+ao);
      }
      #pragma unroll
      for (int j = 0; j < 16; j++) {
        uint32_t bh[2];
        if (TR) {
          uint32_t bb = (uint32_t)(ks*16 + (lane & 15))*1040 + (wn2 + j*8)*2;
          LDSM2T(bh, smb+SW2H+bb);
        } else {
          uint32_t bb = (uint32_t)(wn2 + j*8 + (lane & 7))*144 + (ks*16 + ((lane >> 3) & 1)*8)*2;
          LDSM2(bh, smb+SW2H+bb);
        }
        #pragma unroll
        for (int i = 0; i < 2; i++) {
          MMAH(acc2[i][j], ah[i], bh);
          MMAH(acc2[i][j], al[i], bh);
        }
      }
    }
    __syncthreads();   // protect SHH/SW2 before next hc overwrites
  }
  // epilogue
  int r = lane >> 2, c = (lane & 3)*2;
  #pragma unroll
  for (int i = 0; i < 2; i++)
    #pragma unroll
    for (int half = 0; half < 2; half++) {
      int rl = wm2 + i*16 + r + half*8;
      if (TR) {
        int tok = stok[rl];
        if (tok < 0) continue;
        float w = swgt[rl];
        float* dst = out + (size_t)tok*D_MODEL;
        #pragma unroll
        for (int j = 0; j < 16; j++) {
          int col = wn2 + j*8 + c;
          atomicAdd(dst + col,     acc2[i][j][half*2+0]*w);
          atomicAdd(dst + col + 1, acc2[i][j][half*2+1]*w);
        }
      } else {
        float* dst = out + (size_t)(mbase + rl)*D_MODEL;
        #pragma unroll
        for (int j = 0; j < 16; j++) {
          int col = wn2 + j*8 + c;
          *(float2*)(dst + col) = make_float2(acc2[i][j][half*2+0], acc2[i][j][half*2+1]);
        }
      }
    }
}

// ===================== kernels ==================================================
__global__ void k_zero_region(float* __restrict__ reg) {
  int i = blockIdx.x*256 + threadIdx.x;
  if (i < R_END) reg[i] = 0.f;
}

__global__ __launch_bounds__(128) void k_router(const float* __restrict__ x,
    const float* __restrict__ gw, const float* __restrict__ bias,
    const float* __restrict__ nullp, float* __restrict__ reg) {
  __shared__ float xs[D_MODEL];
  __shared__ float lg[NEXP];
  int t = blockIdx.x, tid = threadIdx.x;
  *(float4*)(xs + tid*4) = *(const float4*)(x + (size_t)t*D_MODEL + tid*4);
  __syncthreads();
  if (tid < NEXP) {
    const float* w = gw + (size_t)tid*D_MODEL;
    float s = 0.f;
    #pragma unroll 8
    for (int k = 0; k < D_MODEL; k += 4) {
      float4 wv = *(const float4*)(w + k);
      s += xs[k]*wv.x + xs[k+1]*wv.y + xs[k+2]*wv.z + xs[k+3]*wv.w;
    }
    lg[tid] = s + bias[tid];
  }
  __syncthreads();
  if (tid == 0) {
    int*   cnt  = (int*)(reg + R_CNT);
    int*   llen = (int*)(reg + R_LLEN);
    float* psum = reg + R_PSUM;
    int*   ltok = (int*)(reg + R_TOK);
    float* lwgt = reg + R_WGT;
    float nv = *nullp;
    int sel[TOPK]; float wj[TOPK]; int nn;
    top8(lg, nv, sel, wj, &nn);
    for (int j = 0; j < TOPK; j++) {
      if (sel[j] >= 0) {
        atomicAdd(&cnt[sel[j]], 1);
        if (t < T0) {
          int pos = atomicAdd(&llen[sel[j]], 1);
          if (pos < CAPL) {
            ltok[sel[j]*CAPL + pos] = t;
            lwgt[sel[j]*CAPL + pos] = wj[j];
          }
        }
      }
    }
    if (nn) atomicAdd((int*)(reg + R_NULL), nn);
    float mr = -1e30f;
    for (int e = 0; e < NEXP; e++) if (lg[e] > mr) mr = lg[e];
    float Z = 0.f;
    for (int e = 0; e < NEXP; e++) Z += __expf(lg[e]-mr);
    float invZ = 1.f/Z;
    for (int e = 0; e < NEXP; e++) atomicAdd(&psum[e], __expf(lg[e]-mr)*invZ);
    float m2 = fmaxf(mr, nv);
    float Z2 = Z*__expf(mr-m2) + (float)NNULL*__expf(nv-m2);
    float lse = m2 + logf(Z2);
    atomicAdd(reg + R_LSE2, lse*lse);
  }
}

__global__ __launch_bounds__(256) void k_ffn_shared(const float* __restrict__ x,
    const float* __restrict__ Wsg, const float* __restrict__ Wsu,
    const float* __restrict__ Wsd, float* __restrict__ out, int mb) {
  extern __shared__ char sm[];
  ffn_tile<false>(sm, x, Wsg, Wsu, Wsd, out, mb + blockIdx.x*64);
}

__global__ __launch_bounds__(256) void k_ffn_routed(const float* __restrict__ x,
    const float* __restrict__ Wg, const float* __restrict__ Wu,
    const float* __restrict__ Wd, float* __restrict__ out,
    const float* __restrict__ reg) {
  extern __shared__ char sm[];
  int e = blockIdx.y;
  int len = min(((const int*)(reg + R_LLEN))[e], CAPL);
  int m0 = blockIdx.x*64;
  if (m0 >= len) return;
  if (threadIdx.x < 64) {
    int m = m0 + threadIdx.x;
    ((int*)(sm+STOK))[threadIdx.x]   = (m < len) ? ((const int*)(reg + R_TOK))[e*CAPL + m] : -1;
    ((float*)(sm+SWGT))[threadIdx.x] = (m < len) ? (reg + R_WGT)[e*CAPL + m] : 0.f;
  }
  __syncthreads();
  ffn_tile<true>(sm, x,
      Wg + (size_t)e*D_MODEL*D_HID, Wu + (size_t)e*D_MODEL*D_HID,
      Wd + (size_t)e*D_HID*D_MODEL, out, 0);
}

// one block per expert: recompute tail-token routing, run routed FFN on them
__global__ __launch_bounds__(256) void k_cleanup(const float* __restrict__ x,
    const float* __restrict__ gw, const float* __restrict__ bias,
    const float* __restrict__ nullp,
    const float* __restrict__ Wg, const float* __restrict__ Wu,
    const float* __restrict__ Wd, float* __restrict__ out) {
  extern __shared__ char sm[];
  __shared__ float clg[8][NEXP];
  __shared__ int   ctok[NTAIL];
  __shared__ float cwgt[NTAIL];
  __shared__ int   ccnt;
  int tid = threadIdx.x, lane = tid & 31, wid = tid >> 5;
  int e = blockIdx.x;
  if (tid == 0) ccnt = 0;
  __syncthreads();
  float nv = *nullp;
  for (int ti = wid; ti < NTAIL; ti += 8) {
    int t = T0 + ti;
    const float4* xr = (const float4*)(x + (size_t)t*D_MODEL);
    #pragma unroll
    for (int sub = 0; sub < 2; sub++) {
      int e2 = lane + sub*32;
      const float4* wr = (const float4*)(gw + (size_t)e2*D_MODEL);
      float s = 0.f;
      #pragma unroll 8
      for (int k = 0; k < D_MODEL/4; k++) {
        float4 a = xr[k], b = wr[k];
        s += a.x*b.x + a.y*b.y + a.z*b.z + a.w*b.w;
      }
      clg[wid][e2] = s + bias[e2];
    }
    __syncwarp();
    if (lane == 0) {
      int sel[TOPK]; float wj[TOPK]; int nn;
      top8(clg[wid], nv, sel, wj, &nn);
      for (int j = 0; j < TOPK; j++)
        if (sel[j] == e) {
          int p = atomicAdd(&ccnt, 1);
          ctok[p] = t; cwgt[p] = wj[j];
        }
    }
    __syncwarp();
  }
  __syncthreads();
  int n = ccnt;
  for (int m0 = 0; m0 < n; m0 += 64) {
    if (tid < 64) {
      int m = m0 + tid;
      ((int*)(sm+STOK))[tid]   = (m < n) ? ctok[m] : -1;
      ((float*)(sm+SWGT))[tid] = (m < n) ? cwgt[m] : 0.f;
    }
    __syncthreads();
    ffn_tile<true>(sm, x,
        Wg + (size_t)e*D_MODEL*D_HID, Wu + (size_t)e*D_MODEL*D_HID,
        Wd + (size_t)e*D_HID*D_MODEL, out, 0);
    __syncthreads();
  }
}

__global__ void k_aux(float* __restrict__ Out, int out_size) {
  if (out_size <= NTOK*D_MODEL) return;
  const float* reg = Out + (size_t)T0*D_MODEL;
  const int* cnt = (const int*)(reg + R_CNT);
  float sc = 0.f;
  for (int e = 0; e < NEXP; e++) sc += (float)cnt[e];
  float denom = fmaxf(sc, 1e-6f);
  float dot = 0.f;
  for (int e = 0; e < NEXP; e++)
    dot += ((float)cnt[e]/denom) * ((reg + R_PSUM)[e]/(float)NTOK);
  float Lbal = (float)NEXP * dot;
  float Lz = reg[R_LSE2] / (float)NTOK;
  float nr = (float)(*(const int*)(reg + R_NULL)) / (float)(NTOK*TOPK);
  float d = nr - 0.5f;
  Out[(size_t)NTOK*D_MODEL] = 0.02f*Lbal + 0.001f*Lz + 0.01f*d*d;
}

// ---------------- launch --------------------------------------------------------
extern "C" void kernel_launch(void* const* d_in, const int* in_sizes, int n_in,
                              void* d_out, int out_size) {
  const float* x     = (const float*)d_in[0];
  const float* gw    = (const float*)d_in[1];
  const float* bias  = (const float*)d_in[2];
  const float* nullp = (const float*)d_in[3];
  const float* Wg    = (const float*)d_in[4];
  const float* Wu    = (const float*)d_in[5];
  const float* Wd    = (const float*)d_in[6];
  const float* Wsg   = (const float*)d_in[7];
  const float* Wsu   = (const float*)d_in[8];
  const float* Wsd   = (const float*)d_in[9];
  float* out = (float*)d_out;
  float* reg = out + (size_t)T0*D_MODEL;

  cudaFuncSetAttribute(k_ffn_shared, cudaFuncAttributeMaxDynamicSharedMemorySize, SMEM_TOT);
  cudaFuncSetAttribute(k_ffn_routed, cudaFuncAttributeMaxDynamicSharedMemorySize, SMEM_TOT);
  cudaFuncSetAttribute(k_cleanup,    cudaFuncAttributeMaxDynamicSharedMemorySize, SMEM_TOT);

  k_zero_region<<<(R_END + 255)/256, 256>>>(reg);
  k_router<<<NTOK, 128>>>(x, gw, bias, nullp, reg);
  // main tokens [0, T0): shared base output, then routed atomicAdd
  k_ffn_shared<<<T0/64, 256, SMEM_TOT>>>(x, Wsg, Wsu, Wsd, out, 0);
  k_ffn_routed<<<dim3(CAPL/64, NEXP), 256, SMEM_TOT>>>(x, Wg, Wu, Wd, out, reg);
  // aux scalar (consumes region stats)
  k_aux<<<1, 1>>>(out, out_size);
  // tail tokens [T0, NTOK): shared pass overwrites metadata region with output,
  // then cleanup recomputes tail routing and adds routed contributions
  k_ffn_shared<<<NTAIL/64, 256, SMEM_TOT>>>(x, Wsg, Wsu, Wsd, out, T0);
  k_cleanup<<<NEXP, 256, SMEM_TOT>>>(x, gw, bias, nullp, Wg, Wu, Wd, out);
}